// round 15
// baseline (speedup 1.0000x reference)
#include <cuda_runtime.h>
#include <cuda_fp16.h>
#include <cstdint>

// ---------------- problem constants ----------------
#define BB        16
#define HD        128
#define NTILES    8192               // 16*256*2 tiles of 128 pixels
#define GRID      148                // one 512-thread CTA per SM
#define NBASE     55                 // 8192 = 148*55 + 52
#define NEXTRA    52
#define STEPC     (256.0f/255.0f)

// ---------------- smem layout (bytes) ----------------
#define PFB       272                // f16 row pitch in bytes (128+8 elems)
#define ACT_SZ    34816              // 128 rows * 272B
#define SM_ACT_E  0
#define SM_ACT_O  34816
#define SM_W2     69632
#define SM_W3     104448
#define SM_B2P    139264             // uint32[64]
#define SM_B3P    139520             // uint32[64]
#define SM_W4     139776             // float[128]
#define SM_L1P_E  140288             // float2[4][128]
#define SM_L1P_O  144384
#define SM_PART_E 148480             // float[4][128]
#define SM_PART_O 150528
#define SM_RED    152576             // float[512]
#define SM_TOTAL  154624

__device__ float        g_partial[GRID];
__device__ unsigned int g_done;      // zero at load; self-wraps each launch

__device__ __forceinline__ uint32_t smem_u32(const void* p) {
    uint32_t a;
    asm("{ .reg .u64 t; cvta.to.shared.u64 t, %1; cvt.u32.u64 %0, t; }"
        : "=r"(a) : "l"(p));
    return a;
}
__device__ __forceinline__ uint32_t tanh_f16x2(uint32_t x) {
    uint32_t y; asm("tanh.approx.f16x2 %0, %1;" : "=r"(y) : "r"(x)); return y;
}
__device__ __forceinline__ uint32_t hadd2(uint32_t a, uint32_t b) {
    uint32_t y; asm("add.f16x2 %0, %1, %2;" : "=r"(y) : "r"(a), "r"(b)); return y;
}

#define LDSM4(r, addr) \
    asm volatile("ldmatrix.sync.aligned.m8n8.x4.shared.b16 {%0,%1,%2,%3}, [%4];" \
        : "=r"((r)[0]), "=r"((r)[1]), "=r"((r)[2]), "=r"((r)[3]) : "r"(addr))

// f16-accumulate MMA, C = 0 (start of a chain)
#define MMAH_Z(d, a, b0, b1) \
    asm volatile("mma.sync.aligned.m16n8k16.row.col.f16.f16.f16.f16 " \
        "{%0,%1}, {%2,%3,%4,%5}, {%6,%7}, {%8,%8};" \
        : "=r"((d)[0]), "=r"((d)[1]) \
        : "r"((a)[0]), "r"((a)[1]), "r"((a)[2]), "r"((a)[3]), \
          "r"(b0), "r"(b1), "r"(0u))

// f16-accumulate MMA, C = D (chain continue)
#define MMAH_A(d, a, b0, b1) \
    asm volatile("mma.sync.aligned.m16n8k16.row.col.f16.f16.f16.f16 " \
        "{%0,%1}, {%2,%3,%4,%5}, {%6,%7}, {%0,%1};" \
        : "+r"((d)[0]), "+r"((d)[1]) \
        : "r"((a)[0]), "r"((a)[1]), "r"((a)[2]), "r"((a)[3]), \
          "r"(b0), "r"(b1))

// pack: lo -> bits[15:0], hi -> bits[31:16]
#define CVT_F16X2(res, lo, hi) \
    asm("cvt.rn.f16x2.f32 %0, %1, %2;" : "=r"(res) : "f"(hi), "f"(lo))

__device__ __forceinline__ float2 unpack_h2(uint32_t p) {
    __half2 h = *reinterpret_cast<const __half2*>(&p);
    return __half22float2(h);
}

// group-scoped barrier: 256 threads of this group only (ids 1 and 2)
#define GBAR(grp) \
    asm volatile("bar.sync %0, 256;" :: "r"((grp) + 1) : "memory")

// 128x128x128 GEMM, kk-outer, pure f16 accumulator chains.
__device__ __forceinline__ void gemm128_h(uint32_t a_base, uint32_t b_base, uint32_t* h)
{
    #pragma unroll
    for (int kk = 0; kk < 8; ++kk) {
        const uint32_t ko = (uint32_t)kk * 32;
        uint32_t b0r[4], b1r[4];
        LDSM4(b0r, b_base + ko);
        LDSM4(b1r, b_base + 16 * PFB + ko);
        #pragma unroll
        for (int mt = 0; mt < 4; ++mt) {
            uint32_t ar[4];
            LDSM4(ar, a_base + (uint32_t)(mt * 16) * PFB + ko);
            uint32_t* hm = h + mt * 8;
            if (kk == 0) {
                MMAH_Z(hm + 0, ar, b0r[0], b0r[1]);
                MMAH_Z(hm + 2, ar, b0r[2], b0r[3]);
                MMAH_Z(hm + 4, ar, b1r[0], b1r[1]);
                MMAH_Z(hm + 6, ar, b1r[2], b1r[3]);
            } else {
                MMAH_A(hm + 0, ar, b0r[0], b0r[1]);
                MMAH_A(hm + 2, ar, b0r[2], b0r[3]);
                MMAH_A(hm + 4, ar, b1r[0], b1r[1]);
                MMAH_A(hm + 6, ar, b1r[2], b1r[3]);
            }
        }
    }
}

__global__ void __launch_bounds__(512, 1)
mlp_mma_kernel(const float* __restrict__ images,
               const float* __restrict__ W1, const float* __restrict__ b1,
               const float* __restrict__ W2, const float* __restrict__ b2,
               const float* __restrict__ W3, const float* __restrict__ b3,
               const float* __restrict__ W4, const float* __restrict__ b4,
               const int*   nptr,
               float* __restrict__ out)
{
    extern __shared__ char smem[];
    __shared__ unsigned int s_last;
    const uint32_t sb = smem_u32(smem);
    const int tid  = threadIdx.x;
    const int grp  = tid >> 8;          // tile-stream group (0 or 1)
    const int gtid = tid & 255;
    const int lane = tid & 31;
    const int wid  = gtid >> 5;
    const int mh   = wid >> 2;          // pixel half: rows [mh*64, +64)
    const int nq   = wid & 3;           // feature quarter: cols [nq*32, +32)
    const int gid  = lane >> 2;
    const int tig  = lane & 3;
    const int blk  = blockIdx.x;

    // per-CTA tile range: 8192 = 148*55 + 52
    const int my_n     = NBASE + (blk < NEXTRA ? 1 : 0);
    const int my_start = blk * NBASE + (blk < NEXTRA ? blk : NEXTRA);
    // group tile stream: tiles my_start + 2t + grp, t in [0, n_g)
    const int n_g = (my_n + 1 - grp) >> 1;

    // ---- stage weights (transposed, f16) — once per persistent CTA ----
    #pragma unroll 4
    for (int i = tid; i < HD * HD; i += 512) {
        int k = i >> 7, n = i & 127;
        uint32_t off = (uint32_t)(n * PFB + k * 2);
        *(__half*)(smem + SM_W2 + off) = __float2half(W2[i]);
        *(__half*)(smem + SM_W3 + off) = __float2half(W3[i]);
    }
    if (tid < 64) {
        uint32_t p2, p3;
        float a2 = b2[2 * tid], c2 = b2[2 * tid + 1];
        float a3 = b3[2 * tid], c3 = b3[2 * tid + 1];
        CVT_F16X2(p2, a2, c2);
        CVT_F16X2(p3, a3, c3);
        ((uint32_t*)(smem + SM_B2P))[tid] = p2;
        ((uint32_t*)(smem + SM_B3P))[tid] = p3;
    }
    if (tid < HD) ((float*)(smem + SM_W4))[tid] = W4[tid];

    const int nv = (nptr != nullptr) ? nptr[0] : 0;

    // W1 params in registers (gtid<128 of EACH group) — GMEM read once
    float w1x = 0.0f, w1y = 0.0f, w1t = 0.0f, b1v = 0.0f;
    if (gtid < HD) {
        w1x = W1[gtid];
        w1y = W1[HD + gtid];
        w1t = W1[2 * HD + gtid];
        b1v = b1[gtid];
    }

    const float b4v = b4[0];
    const uint32_t* b2p = (const uint32_t*)(smem + SM_B2P);
    const uint32_t* b3p = (const uint32_t*)(smem + SM_B3P);
    const float* w4s = (const float*)(smem + SM_W4);

    // per-group buffers
    char*   acts  = smem + (grp ? SM_ACT_O  : SM_ACT_E);
    float*  part  = (float*) (smem + (grp ? SM_PART_O : SM_PART_E));
    float2* l1p4  = (float2*)(smem + (grp ? SM_L1P_O  : SM_L1P_E));
    const uint32_t acts_u = sb + (grp ? SM_ACT_O : SM_ACT_E);

    const uint32_t a_base = acts_u
        + (uint32_t)((mh * 64 + (lane & 15)) * PFB + (lane >> 4) * 16);
    const uint32_t b_row = (uint32_t)((nq * 32 + ((lane >> 4) << 3) + (lane & 7)) * PFB
                                      + ((lane >> 3) & 1) * 16);
    const uint32_t b_base2 = sb + SM_W2 + b_row;
    const uint32_t b_base3 = sb + SM_W3 + b_row;

    __syncthreads();   // weights staged; groups now run independently

    float lacc = 0.0f;

    for (int g0 = 0; g0 < n_g; g0 += 4) {
        const int gn = (n_g - g0 < 4) ? (n_g - g0) : 4;

        // ---- refill layer-1 params for this group-of-4 (register-fed) ----
        if (gtid < HD) {
            #pragma unroll
            for (int j = 0; j < 4; ++j) {
                if (j < gn) {
                    const int tile = my_start + 2 * (g0 + j) + grp;
                    const int bb = tile >> 9;
                    const int rr = (tile >> 1) & 255;
                    const float tv = (float)(bb + nv * BB);
                    const float xr = -128.0f + (float)rr * STEPC;
                    float2 v;
                    v.x = fmaf(xr, w1x, fmaf(tv, w1t, b1v));
                    v.y = w1y;
                    l1p4[j * HD + gtid] = v;
                }
            }
        }
        GBAR(grp);

        for (int j = 0; j < gn; ++j) {
            const int tile = my_start + 2 * (g0 + j) + grp;
            const int b  = tile >> 9;
            const int r  = (tile >> 1) & 255;
            const int c0 = (tile & 1) << 7;

            // ---- prefetch image pixel (consumed far later) ----
            float img = 0.0f;
            if (gtid < 128)
                img = images[(size_t)(((b << 8) + r) << 8) + c0 + gtid];

            // ---- layer 1 -> acts (f16), packed tanh ----
            {
                const int p  = gtid & 127;
                const int hf = gtid >> 7;
                const float yc = -128.0f + (float)(c0 + p) * STEPC;
                const float2* l1p = l1p4 + j * HD;
                char* arow = acts + p * PFB + hf * 128;
                #pragma unroll
                for (int jj = 0; jj < 32; ++jj) {
                    float2 q0 = l1p[hf * 64 + 2 * jj];
                    float2 q1 = l1p[hf * 64 + 2 * jj + 1];
                    float v0 = fmaf(yc, q0.y, q0.x);
                    float v1 = fmaf(yc, q1.y, q1.x);
                    uint32_t pk; CVT_F16X2(pk, v0, v1);
                    *(uint32_t*)(arow + 4 * jj) = tanh_f16x2(pk);
                }
            }
            GBAR(grp);

            // ---- layer 2: GEMM (f16 acc) + packed bias+tanh (in place) ----
            {
                uint32_t h[32];
                gemm128_h(a_base, b_base2, h);
                GBAR(grp);   // all reads of acts complete
                #pragma unroll
                for (int mt = 0; mt < 4; ++mt) {
                    const int row = mh * 64 + mt * 16 + gid;
                    #pragma unroll
                    for (int ns = 0; ns < 4; ++ns) {
                        const uint32_t* c = &h[(mt * 4 + ns) * 2];
                        const int pair = nq * 16 + ns * 4 + tig;
                        uint32_t bb = b2p[pair];
                        uint32_t p01 = tanh_f16x2(hadd2(c[0], bb));
                        uint32_t p23 = tanh_f16x2(hadd2(c[1], bb));
                        *(uint32_t*)(acts + row * PFB + pair * 4) = p01;
                        *(uint32_t*)(acts + (row + 8) * PFB + pair * 4) = p23;
                    }
                }
            }
            GBAR(grp);

            // ---- layer 3: GEMM (f16 acc) + packed bias+tanh + W4 dot ----
            {
                uint32_t h[32];
                gemm128_h(a_base, b_base3, h);
                #pragma unroll
                for (int mt = 0; mt < 4; ++mt) {
                    float p0 = 0.0f, p1 = 0.0f;
                    #pragma unroll
                    for (int ns = 0; ns < 4; ++ns) {
                        const uint32_t* c = &h[(mt * 4 + ns) * 2];
                        const int pair = nq * 16 + ns * 4 + tig;
                        uint32_t bb = b3p[pair];
                        float w0 = w4s[2 * pair], w1 = w4s[2 * pair + 1];
                        float2 f01 = unpack_h2(tanh_f16x2(hadd2(c[0], bb)));
                        float2 f23 = unpack_h2(tanh_f16x2(hadd2(c[1], bb)));
                        p0 = fmaf(f01.x, w0, p0);
                        p0 = fmaf(f01.y, w1, p0);
                        p1 = fmaf(f23.x, w0, p1);
                        p1 = fmaf(f23.y, w1, p1);
                    }
                    p0 += __shfl_xor_sync(0xFFFFFFFFu, p0, 1);
                    p0 += __shfl_xor_sync(0xFFFFFFFFu, p0, 2);
                    p1 += __shfl_xor_sync(0xFFFFFFFFu, p1, 1);
                    p1 += __shfl_xor_sync(0xFFFFFFFFu, p1, 2);
                    if (tig == 0) {
                        const int row = mh * 64 + mt * 16 + gid;
                        part[nq * 128 + row]     = p0;
                        part[nq * 128 + row + 8] = p1;
                    }
                }
            }
            GBAR(grp);   // part complete; orders acts/L1P vs next tile

            // ---- recon + squared error ----
            if (gtid < 128) {
                const int p = gtid;
                float recon = b4v + part[p] + part[128 + p]
                            + part[256 + p] + part[384 + p];
                float e = img - recon;
                lacc = fmaf(e, e, lacc);
            }
        }
    }

    // ---- CTA-wide reduction over 512 threads ----
    __syncthreads();
    float* red = (float*)(smem + SM_RED);
    red[tid] = lacc;
    __syncthreads();
    #pragma unroll
    for (int s = 256; s > 0; s >>= 1) {
        if (tid < s) red[tid] += red[tid + s];
        __syncthreads();
    }

    // ---- publish partial; last CTA reduces (counter self-wraps) ----
    if (tid == 0) {
        g_partial[blk] = red[0];
        __threadfence();
        unsigned int old = atomicInc(&g_done, GRID - 1);
        s_last = (old == GRID - 1) ? 1u : 0u;
    }
    __syncthreads();
    if (s_last) {
        __threadfence();   // acquire: g_partial writes visible to whole block
        float a = 0.0f;
        for (int i = tid; i < GRID; i += 512) a += g_partial[i];
        red[tid] = a;
        __syncthreads();
        #pragma unroll
        for (int s = 256; s > 0; s >>= 1) {
            if (tid < s) red[tid] += red[tid + s];
            __syncthreads();
        }
        if (tid == 0)
            out[0] = red[0] * (1.0f / (float)(BB * 256 * 256));
    }
}

extern "C" void kernel_launch(void* const* d_in, const int* in_sizes, int n_in,
                              void* d_out, int out_size)
{
    const float* images = (const float*)d_in[0];
    const float* W1     = (const float*)d_in[1];
    const float* b1     = (const float*)d_in[2];
    const float* W2     = (const float*)d_in[3];
    const float* b2     = (const float*)d_in[4];
    const float* W3     = (const float*)d_in[5];
    const float* b3     = (const float*)d_in[6];
    const float* W4     = (const float*)d_in[7];
    const float* b4     = (const float*)d_in[8];
    const int*   nptr   = (n_in > 10) ? (const int*)d_in[10] : nullptr;

    cudaFuncSetAttribute(mlp_mma_kernel,
                         cudaFuncAttributeMaxDynamicSharedMemorySize, SM_TOTAL);

    mlp_mma_kernel<<<GRID, 512, SM_TOTAL>>>(images, W1, b1, W2, b2,
                                            W3, b3, W4, b4, nptr,
                                            (float*)d_out);
}

// round 16
// speedup vs baseline: 1.0861x; 1.0861x over previous
#include <cuda_runtime.h>
#include <cuda_fp16.h>
#include <cstdint>

// ---------------- problem constants ----------------
#define BB        16
#define HD        128
#define NTILES    8192               // 16*256*2 tiles of 128 pixels
#define GRID      296                // 148 SM x 2 CTAs: exactly one wave
#define NBASE     27                 // 8192 = 296*27 + 200
#define NEXTRA    200
#define STEPC     (256.0f/255.0f)

// ---------------- smem layout (bytes) ----------------
#define PFB       272                // f16 row pitch in bytes (128+8 elems)
#define SM_ACT    0
#define SM_W2     34816
#define SM_W3     69632
#define SM_B2P    104448             // uint32[64]  b2 packed f16x2
#define SM_B3P    104704             // uint32[64]
#define SM_W4     104960             // float[128]
#define SM_L1P4   105472             // float2[4][128] rolling group buffer
#define SM_PART   109568             // float[4][128]
#define SM_RED    SM_PART            // reduction reuses part (after loop)
#define SM_TOTAL  111616

__device__ float        g_partial[GRID];
__device__ unsigned int g_done;      // zero at load; self-wraps each launch

__device__ __forceinline__ uint32_t smem_u32(const void* p) {
    uint32_t a;
    asm("{ .reg .u64 t; cvta.to.shared.u64 t, %1; cvt.u32.u64 %0, t; }"
        : "=r"(a) : "l"(p));
    return a;
}
__device__ __forceinline__ uint32_t tanh_f16x2(uint32_t x) {
    uint32_t y; asm("tanh.approx.f16x2 %0, %1;" : "=r"(y) : "r"(x)); return y;
}
__device__ __forceinline__ uint32_t hadd2(uint32_t a, uint32_t b) {
    uint32_t y; asm("add.f16x2 %0, %1, %2;" : "=r"(y) : "r"(a), "r"(b)); return y;
}

#define LDSM4(r, addr) \
    asm volatile("ldmatrix.sync.aligned.m8n8.x4.shared.b16 {%0,%1,%2,%3}, [%4];" \
        : "=r"((r)[0]), "=r"((r)[1]), "=r"((r)[2]), "=r"((r)[3]) : "r"(addr))

// f16-accumulate MMA, C = 0 (start of a chain)
#define MMAH_Z(d, a, b0, b1) \
    asm volatile("mma.sync.aligned.m16n8k16.row.col.f16.f16.f16.f16 " \
        "{%0,%1}, {%2,%3,%4,%5}, {%6,%7}, {%8,%8};" \
        : "=r"((d)[0]), "=r"((d)[1]) \
        : "r"((a)[0]), "r"((a)[1]), "r"((a)[2]), "r"((a)[3]), \
          "r"(b0), "r"(b1), "r"(0u))

// f16-accumulate MMA, C = D (chain continue)
#define MMAH_A(d, a, b0, b1) \
    asm volatile("mma.sync.aligned.m16n8k16.row.col.f16.f16.f16.f16 " \
        "{%0,%1}, {%2,%3,%4,%5}, {%6,%7}, {%0,%1};" \
        : "+r"((d)[0]), "+r"((d)[1]) \
        : "r"((a)[0]), "r"((a)[1]), "r"((a)[2]), "r"((a)[3]), \
          "r"(b0), "r"(b1))

// pack: lo -> bits[15:0], hi -> bits[31:16]
#define CVT_F16X2(res, lo, hi) \
    asm("cvt.rn.f16x2.f32 %0, %1, %2;" : "=r"(res) : "f"(hi), "f"(lo))

__device__ __forceinline__ float2 unpack_h2(uint32_t p) {
    __half2 h = *reinterpret_cast<const __half2*>(&p);
    return __half22float2(h);
}

// 128x128x128 GEMM, kk-outer, pure f16 accumulator chains.
__device__ __forceinline__ void gemm128_h(uint32_t a_base, uint32_t b_base, uint32_t* h)
{
    #pragma unroll
    for (int kk = 0; kk < 8; ++kk) {
        const uint32_t ko = (uint32_t)kk * 32;
        uint32_t b0r[4], b1r[4];
        LDSM4(b0r, b_base + ko);
        LDSM4(b1r, b_base + 16 * PFB + ko);
        #pragma unroll
        for (int mt = 0; mt < 4; ++mt) {
            uint32_t ar[4];
            LDSM4(ar, a_base + (uint32_t)(mt * 16) * PFB + ko);
            uint32_t* hm = h + mt * 8;
            if (kk == 0) {
                MMAH_Z(hm + 0, ar, b0r[0], b0r[1]);
                MMAH_Z(hm + 2, ar, b0r[2], b0r[3]);
                MMAH_Z(hm + 4, ar, b1r[0], b1r[1]);
                MMAH_Z(hm + 6, ar, b1r[2], b1r[3]);
            } else {
                MMAH_A(hm + 0, ar, b0r[0], b0r[1]);
                MMAH_A(hm + 2, ar, b0r[2], b0r[3]);
                MMAH_A(hm + 4, ar, b1r[0], b1r[1]);
                MMAH_A(hm + 6, ar, b1r[2], b1r[3]);
            }
        }
    }
}

__global__ void __launch_bounds__(256, 2)
mlp_mma_kernel(const float* __restrict__ images,
               const float* __restrict__ W1, const float* __restrict__ b1,
               const float* __restrict__ W2, const float* __restrict__ b2,
               const float* __restrict__ W3, const float* __restrict__ b3,
               const float* __restrict__ W4, const float* __restrict__ b4,
               const int*   nptr,
               float* __restrict__ out)
{
    extern __shared__ char smem[];
    __shared__ unsigned int s_last;
    const uint32_t sb = smem_u32(smem);
    const int tid  = threadIdx.x;
    const int lane = tid & 31;
    const int wid  = tid >> 5;
    const int mh   = wid >> 2;          // pixel half: rows [mh*64, +64)
    const int nq   = wid & 3;           // feature quarter: cols [nq*32, +32)
    const int gid  = lane >> 2;
    const int tig  = lane & 3;
    const int blk  = blockIdx.x;

    // static persistent tile range: 8192 = 296*27 + 200
    const int my_n     = NBASE + (blk < NEXTRA ? 1 : 0);
    const int my_start = blk * NBASE + (blk < NEXTRA ? blk : NEXTRA);

    // ---- stage weights (transposed, f16) — once per persistent CTA ----
    #pragma unroll 4
    for (int i = tid; i < HD * HD; i += 256) {
        int k = i >> 7, n = i & 127;
        uint32_t off = (uint32_t)(n * PFB + k * 2);
        *(__half*)(smem + SM_W2 + off) = __float2half(W2[i]);
        *(__half*)(smem + SM_W3 + off) = __float2half(W3[i]);
    }
    if (tid < 64) {
        uint32_t p2, p3;
        float a2 = b2[2 * tid], c2 = b2[2 * tid + 1];
        float a3 = b3[2 * tid], c3 = b3[2 * tid + 1];
        CVT_F16X2(p2, a2, c2);
        CVT_F16X2(p3, a3, c3);
        ((uint32_t*)(smem + SM_B2P))[tid] = p2;
        ((uint32_t*)(smem + SM_B3P))[tid] = p3;
    }
    if (tid < HD) ((float*)(smem + SM_W4))[tid] = W4[tid];

    const int nv = (nptr != nullptr) ? nptr[0] : 0;

    // W1 params held in registers (tid<128) for group refills — GMEM read once
    float w1x = 0.0f, w1y = 0.0f, w1t = 0.0f, b1v = 0.0f;
    if (tid < HD) {
        w1x = W1[tid];
        w1y = W1[HD + tid];
        w1t = W1[2 * HD + tid];
        b1v = b1[tid];
    }

    const float b4v = b4[0];
    const uint32_t* b2p = (const uint32_t*)(smem + SM_B2P);
    const uint32_t* b3p = (const uint32_t*)(smem + SM_B3P);
    const float* w4s = (const float*)(smem + SM_W4);
    float* part = (float*)(smem + SM_PART);
    float2* l1p4 = (float2*)(smem + SM_L1P4);

    const uint32_t a_base = sb + SM_ACT
        + (uint32_t)((mh * 64 + (lane & 15)) * PFB + (lane >> 4) * 16);
    const uint32_t b_row = (uint32_t)((nq * 32 + ((lane >> 4) << 3) + (lane & 7)) * PFB
                                      + ((lane >> 3) & 1) * 16);
    const uint32_t b_base2 = sb + SM_W2 + b_row;
    const uint32_t b_base3 = sb + SM_W3 + b_row;

    float lacc = 0.0f;

    for (int g0 = 0; g0 < my_n; g0 += 4) {
        const int gn = (my_n - g0 < 4) ? (my_n - g0) : 4;

        // ---- refill layer-1 params for this group (register-fed, no GMEM) ----
        if (tid < HD) {
            #pragma unroll
            for (int j = 0; j < 4; ++j) {
                if (j < gn) {
                    const int tile = my_start + g0 + j;
                    const int bb = tile >> 9;
                    const int rr = (tile >> 1) & 255;
                    const float tv = (float)(bb + nv * BB);
                    const float xr = -128.0f + (float)rr * STEPC;
                    float2 v;
                    v.x = fmaf(xr, w1x, fmaf(tv, w1t, b1v));
                    v.y = w1y;
                    l1p4[j * HD + tid] = v;
                }
            }
        }
        __syncthreads();   // (also covers initial weight staging on g0==0)

        for (int j = 0; j < gn; ++j) {
            const int tile = my_start + g0 + j;
            const int b  = tile >> 9;
            const int r  = (tile >> 1) & 255;
            const int c0 = (tile & 1) << 7;

            // ---- prefetch image pixel (consumed ~9000 cyc later) ----
            float img = 0.0f;
            if (tid < 128)
                img = images[(size_t)(((b << 8) + r) << 8) + c0 + tid];

            // ---- layer 1 -> acts (f16), packed tanh, STS.128 conflict-free ----
            {
                const int p  = tid & 127;
                const int hf = tid >> 7;
                const float yc = -128.0f + (float)(c0 + p) * STEPC;
                // 64 float2 params of this half = 32 float4 (16B aligned)
                const float4* l1pv = (const float4*)(l1p4 + j * HD + hf * 64);
                char* arow = smem + SM_ACT + p * PFB + hf * 128;
                #pragma unroll
                for (int jj = 0; jj < 8; ++jj) {
                    uint4 st;
                    uint32_t pk[4];
                    #pragma unroll
                    for (int q = 0; q < 4; ++q) {
                        float4 f = l1pv[jj * 4 + q];   // {base0,w1y0,base1,w1y1}
                        float v0 = fmaf(yc, f.y, f.x);
                        float v1 = fmaf(yc, f.w, f.z);
                        uint32_t pp; CVT_F16X2(pp, v0, v1);
                        pk[q] = tanh_f16x2(pp);
                    }
                    st.x = pk[0]; st.y = pk[1]; st.z = pk[2]; st.w = pk[3];
                    *(uint4*)(arow + 16 * jj) = st;
                }
            }
            __syncthreads();

            // ---- layer 2: GEMM (f16 acc) + packed bias+tanh (in place) ----
            {
                uint32_t h[32];
                gemm128_h(a_base, b_base2, h);
                __syncthreads();   // all reads of acts complete
                #pragma unroll
                for (int mt = 0; mt < 4; ++mt) {
                    const int row = mh * 64 + mt * 16 + gid;
                    #pragma unroll
                    for (int ns = 0; ns < 4; ++ns) {
                        const uint32_t* c = &h[(mt * 4 + ns) * 2];
                        const int pair = nq * 16 + ns * 4 + tig;
                        uint32_t bb = b2p[pair];
                        uint32_t p01 = tanh_f16x2(hadd2(c[0], bb));
                        uint32_t p23 = tanh_f16x2(hadd2(c[1], bb));
                        *(uint32_t*)(smem + SM_ACT + row * PFB + pair * 4) = p01;
                        *(uint32_t*)(smem + SM_ACT + (row + 8) * PFB + pair * 4) = p23;
                    }
                }
            }
            __syncthreads();

            // ---- layer 3: GEMM (f16 acc) + packed bias+tanh + W4 dot ----
            {
                uint32_t h[32];
                gemm128_h(a_base, b_base3, h);
                #pragma unroll
                for (int mt = 0; mt < 4; ++mt) {
                    float p0 = 0.0f, p1 = 0.0f;
                    #pragma unroll
                    for (int ns = 0; ns < 4; ++ns) {
                        const uint32_t* c = &h[(mt * 4 + ns) * 2];
                        const int pair = nq * 16 + ns * 4 + tig;
                        uint32_t bb = b3p[pair];
                        float w0 = w4s[2 * pair], w1 = w4s[2 * pair + 1];
                        float2 f01 = unpack_h2(tanh_f16x2(hadd2(c[0], bb)));
                        float2 f23 = unpack_h2(tanh_f16x2(hadd2(c[1], bb)));
                        p0 = fmaf(f01.x, w0, p0);
                        p0 = fmaf(f01.y, w1, p0);
                        p1 = fmaf(f23.x, w0, p1);
                        p1 = fmaf(f23.y, w1, p1);
                    }
                    p0 += __shfl_xor_sync(0xFFFFFFFFu, p0, 1);
                    p0 += __shfl_xor_sync(0xFFFFFFFFu, p0, 2);
                    p1 += __shfl_xor_sync(0xFFFFFFFFu, p1, 1);
                    p1 += __shfl_xor_sync(0xFFFFFFFFu, p1, 2);
                    if (tig == 0) {
                        const int row = mh * 64 + mt * 16 + gid;
                        part[nq * 128 + row]     = p0;
                        part[nq * 128 + row + 8] = p1;
                    }
                }
            }
            __syncthreads();   // part complete; orders acts/L1P vs next tile

            // ---- recon + squared error ----
            if (tid < 128) {
                const int p = tid;
                float recon = b4v + part[p] + part[128 + p]
                            + part[256 + p] + part[384 + p];
                float e = img - recon;
                lacc = fmaf(e, e, lacc);
            }
        }
    }

    // ---- block reduction (reuses part area; loop is done) ----
    __syncthreads();
    float* red = (float*)(smem + SM_RED);
    red[tid] = lacc;
    __syncthreads();
    #pragma unroll
    for (int s = 128; s > 0; s >>= 1) {
        if (tid < s) red[tid] += red[tid + s];
        __syncthreads();
    }

    // ---- publish partial; last CTA reduces (counter self-wraps per launch) ----
    if (tid == 0) {
        g_partial[blk] = red[0];
        __threadfence();
        unsigned int old = atomicInc(&g_done, GRID - 1);
        s_last = (old == GRID - 1) ? 1u : 0u;
    }
    __syncthreads();
    if (s_last) {
        __threadfence();   // acquire: g_partial writes visible to whole block
        float a = 0.0f;
        for (int i = tid; i < GRID; i += 256) a += g_partial[i];
        red[tid] = a;
        __syncthreads();
        #pragma unroll
        for (int s = 128; s > 0; s >>= 1) {
            if (tid < s) red[tid] += red[tid + s];
            __syncthreads();
        }
        if (tid == 0)
            out[0] = red[0] * (1.0f / (float)(BB * 256 * 256));
    }
}

extern "C" void kernel_launch(void* const* d_in, const int* in_sizes, int n_in,
                              void* d_out, int out_size)
{
    const float* images = (const float*)d_in[0];
    const float* W1     = (const float*)d_in[1];
    const float* b1     = (const float*)d_in[2];
    const float* W2     = (const float*)d_in[3];
    const float* b2     = (const float*)d_in[4];
    const float* W3     = (const float*)d_in[5];
    const float* b3     = (const float*)d_in[6];
    const float* W4     = (const float*)d_in[7];
    const float* b4     = (const float*)d_in[8];
    const int*   nptr   = (n_in > 10) ? (const int*)d_in[10] : nullptr;

    cudaFuncSetAttribute(mlp_mma_kernel,
                         cudaFuncAttributeMaxDynamicSharedMemorySize, SM_TOTAL);

    mlp_mma_kernel<<<GRID, 256, SM_TOTAL>>>(images, W1, b1, W2, b2,
                                            W3, b3, W4, b4, nptr,
                                            (float*)d_out);
}

// round 17
// speedup vs baseline: 1.1145x; 1.0261x over previous
#include <cuda_runtime.h>
#include <cuda_fp16.h>
#include <cstdint>

// ---------------- problem constants ----------------
#define BB        16
#define HD        128
#define NTILES    8192               // 16*256*2 tiles of 128 pixels
#define GRID      296                // 148 SM x 2 CTAs: exactly one wave
#define NBASE     27                 // 8192 = 296*27 + 200
#define NEXTRA    200
#define STEPC     (256.0f/255.0f)

// ---------------- smem layout (bytes) ----------------
#define PFB       272                // f16 row pitch in bytes (128+8 elems)
#define SM_ACT    0
#define SM_W2     34816
#define SM_W3     69632
#define SM_B2P    104448             // uint32[64]  b2 packed f16x2
#define SM_B3P    104704             // uint32[64]
#define SM_W4     104960             // float[128]
#define SM_L1P4   105472             // float2[4][128] rolling group buffer
#define SM_PART   109568             // float[4][128]
#define SM_RED    SM_PART            // reduction reuses part (after loop)
#define SM_TOTAL  111616

__device__ float        g_partial[GRID];
__device__ unsigned int g_done;      // zero at load; self-wraps each launch

__device__ __forceinline__ uint32_t smem_u32(const void* p) {
    uint32_t a;
    asm("{ .reg .u64 t; cvta.to.shared.u64 t, %1; cvt.u32.u64 %0, t; }"
        : "=r"(a) : "l"(p));
    return a;
}
__device__ __forceinline__ uint32_t tanh_f16x2(uint32_t x) {
    uint32_t y; asm("tanh.approx.f16x2 %0, %1;" : "=r"(y) : "r"(x)); return y;
}
__device__ __forceinline__ uint32_t hadd2(uint32_t a, uint32_t b) {
    uint32_t y; asm("add.f16x2 %0, %1, %2;" : "=r"(y) : "r"(a), "r"(b)); return y;
}

#define LDSM4(r, addr) \
    asm volatile("ldmatrix.sync.aligned.m8n8.x4.shared.b16 {%0,%1,%2,%3}, [%4];" \
        : "=r"((r)[0]), "=r"((r)[1]), "=r"((r)[2]), "=r"((r)[3]) : "r"(addr))

// f16-accumulate MMA, C = 0 (start of a chain)
#define MMAH_Z(d, a, b0, b1) \
    asm volatile("mma.sync.aligned.m16n8k16.row.col.f16.f16.f16.f16 " \
        "{%0,%1}, {%2,%3,%4,%5}, {%6,%7}, {%8,%8};" \
        : "=r"((d)[0]), "=r"((d)[1]) \
        : "r"((a)[0]), "r"((a)[1]), "r"((a)[2]), "r"((a)[3]), \
          "r"(b0), "r"(b1), "r"(0u))

// f16-accumulate MMA, C = D (chain continue)
#define MMAH_A(d, a, b0, b1) \
    asm volatile("mma.sync.aligned.m16n8k16.row.col.f16.f16.f16.f16 " \
        "{%0,%1}, {%2,%3,%4,%5}, {%6,%7}, {%0,%1};" \
        : "+r"((d)[0]), "+r"((d)[1]) \
        : "r"((a)[0]), "r"((a)[1]), "r"((a)[2]), "r"((a)[3]), \
          "r"(b0), "r"(b1))

// pack: lo -> bits[15:0], hi -> bits[31:16]
#define CVT_F16X2(res, lo, hi) \
    asm("cvt.rn.f16x2.f32 %0, %1, %2;" : "=r"(res) : "f"(hi), "f"(lo))

__device__ __forceinline__ float2 unpack_h2(uint32_t p) {
    __half2 h = *reinterpret_cast<const __half2*>(&p);
    return __half22float2(h);
}

// half-CTA barrier: the 4 warps (128 threads) of one pixel half
#define HBAR(mh) \
    asm volatile("bar.sync %0, 128;" :: "r"((mh) + 1) : "memory")

// 128x128x128 GEMM, kk-outer, pure f16 accumulator chains.
__device__ __forceinline__ void gemm128_h(uint32_t a_base, uint32_t b_base, uint32_t* h)
{
    #pragma unroll
    for (int kk = 0; kk < 8; ++kk) {
        const uint32_t ko = (uint32_t)kk * 32;
        uint32_t b0r[4], b1r[4];
        LDSM4(b0r, b_base + ko);
        LDSM4(b1r, b_base + 16 * PFB + ko);
        #pragma unroll
        for (int mt = 0; mt < 4; ++mt) {
            uint32_t ar[4];
            LDSM4(ar, a_base + (uint32_t)(mt * 16) * PFB + ko);
            uint32_t* hm = h + mt * 8;
            if (kk == 0) {
                MMAH_Z(hm + 0, ar, b0r[0], b0r[1]);
                MMAH_Z(hm + 2, ar, b0r[2], b0r[3]);
                MMAH_Z(hm + 4, ar, b1r[0], b1r[1]);
                MMAH_Z(hm + 6, ar, b1r[2], b1r[3]);
            } else {
                MMAH_A(hm + 0, ar, b0r[0], b0r[1]);
                MMAH_A(hm + 2, ar, b0r[2], b0r[3]);
                MMAH_A(hm + 4, ar, b1r[0], b1r[1]);
                MMAH_A(hm + 6, ar, b1r[2], b1r[3]);
            }
        }
    }
}

__global__ void __launch_bounds__(256, 2)
mlp_mma_kernel(const float* __restrict__ images,
               const float* __restrict__ W1, const float* __restrict__ b1,
               const float* __restrict__ W2, const float* __restrict__ b2,
               const float* __restrict__ W3, const float* __restrict__ b3,
               const float* __restrict__ W4, const float* __restrict__ b4,
               const int*   nptr,
               float* __restrict__ out)
{
    extern __shared__ char smem[];
    __shared__ unsigned int s_last;
    const uint32_t sb = smem_u32(smem);
    const int tid  = threadIdx.x;
    const int lane = tid & 31;
    const int wid  = tid >> 5;
    const int mh   = wid >> 2;          // pixel half: rows [mh*64, +64)
    const int nq   = wid & 3;           // feature quarter: cols [nq*32, +32)
    const int gid  = lane >> 2;
    const int tig  = lane & 3;
    const int blk  = blockIdx.x;

    // static persistent tile range: 8192 = 296*27 + 200
    const int my_n     = NBASE + (blk < NEXTRA ? 1 : 0);
    const int my_start = blk * NBASE + (blk < NEXTRA ? blk : NEXTRA);

    // ---- stage weights (transposed, f16) — once per persistent CTA ----
    #pragma unroll 4
    for (int i = tid; i < HD * HD; i += 256) {
        int k = i >> 7, n = i & 127;
        uint32_t off = (uint32_t)(n * PFB + k * 2);
        *(__half*)(smem + SM_W2 + off) = __float2half(W2[i]);
        *(__half*)(smem + SM_W3 + off) = __float2half(W3[i]);
    }
    if (tid < 64) {
        uint32_t p2, p3;
        float a2 = b2[2 * tid], c2 = b2[2 * tid + 1];
        float a3 = b3[2 * tid], c3 = b3[2 * tid + 1];
        CVT_F16X2(p2, a2, c2);
        CVT_F16X2(p3, a3, c3);
        ((uint32_t*)(smem + SM_B2P))[tid] = p2;
        ((uint32_t*)(smem + SM_B3P))[tid] = p3;
    }
    if (tid < HD) ((float*)(smem + SM_W4))[tid] = W4[tid];

    const int nv = (nptr != nullptr) ? nptr[0] : 0;

    // W1 params held in registers (tid<128) for group refills — GMEM read once
    float w1x = 0.0f, w1y = 0.0f, w1t = 0.0f, b1v = 0.0f;
    if (tid < HD) {
        w1x = W1[tid];
        w1y = W1[HD + tid];
        w1t = W1[2 * HD + tid];
        b1v = b1[tid];
    }

    const float b4v = b4[0];
    const uint32_t* b2p = (const uint32_t*)(smem + SM_B2P);
    const uint32_t* b3p = (const uint32_t*)(smem + SM_B3P);
    const float* w4s = (const float*)(smem + SM_W4);
    float* part = (float*)(smem + SM_PART);
    float2* l1p4 = (float2*)(smem + SM_L1P4);

    const uint32_t a_base = sb + SM_ACT
        + (uint32_t)((mh * 64 + (lane & 15)) * PFB + (lane >> 4) * 16);
    const uint32_t b_row = (uint32_t)((nq * 32 + ((lane >> 4) << 3) + (lane & 7)) * PFB
                                      + ((lane >> 3) & 1) * 16);
    const uint32_t b_base2 = sb + SM_W2 + b_row;
    const uint32_t b_base3 = sb + SM_W3 + b_row;

    float lacc = 0.0f;

    for (int g0 = 0; g0 < my_n; g0 += 4) {
        const int gn = (my_n - g0 < 4) ? (my_n - g0) : 4;

        // ---- refill layer-1 params for this group (register-fed, no GMEM) ----
        if (tid < HD) {
            #pragma unroll
            for (int j = 0; j < 4; ++j) {
                if (j < gn) {
                    const int tile = my_start + g0 + j;
                    const int bb = tile >> 9;
                    const int rr = (tile >> 1) & 255;
                    const float tv = (float)(bb + nv * BB);
                    const float xr = -128.0f + (float)rr * STEPC;
                    float2 v;
                    v.x = fmaf(xr, w1x, fmaf(tv, w1t, b1v));
                    v.y = w1y;
                    l1p4[j * HD + tid] = v;
                }
            }
        }
        __syncthreads();   // (also covers initial weight staging on g0==0)

        for (int j = 0; j < gn; ++j) {
            const int tile = my_start + g0 + j;
            const int b  = tile >> 9;
            const int r  = (tile >> 1) & 255;
            const int c0 = (tile & 1) << 7;

            // ---- prefetch image pixel (consumed ~9000 cyc later) ----
            float img = 0.0f;
            if (tid < 128)
                img = images[(size_t)(((b << 8) + r) << 8) + c0 + tid];

            // ---- layer 1 -> acts (f16), packed tanh, STS.128 conflict-free ----
            {
                const int p  = tid & 127;
                const int hf = tid >> 7;
                const float yc = -128.0f + (float)(c0 + p) * STEPC;
                // 64 float2 params of this half = 32 float4 (16B aligned)
                const float4* l1pv = (const float4*)(l1p4 + j * HD + hf * 64);
                char* arow = smem + SM_ACT + p * PFB + hf * 128;
                #pragma unroll
                for (int jj = 0; jj < 8; ++jj) {
                    uint4 st;
                    uint32_t pk[4];
                    #pragma unroll
                    for (int q = 0; q < 4; ++q) {
                        float4 f = l1pv[jj * 4 + q];   // {base0,w1y0,base1,w1y1}
                        float v0 = fmaf(yc, f.y, f.x);
                        float v1 = fmaf(yc, f.w, f.z);
                        uint32_t pp; CVT_F16X2(pp, v0, v1);
                        pk[q] = tanh_f16x2(pp);
                    }
                    st.x = pk[0]; st.y = pk[1]; st.z = pk[2]; st.w = pk[3];
                    *(uint4*)(arow + 16 * jj) = st;
                }
            }
            __syncthreads();   // full: layer-1 writers span both halves

            // ---- layer 2: GEMM (f16 acc) + packed bias+tanh (in place) ----
            // rows [mh*64,+64) are read AND written only by this half's
            // 4 warps -> half-CTA barriers suffice around the in-place swap.
            {
                uint32_t h[32];
                gemm128_h(a_base, b_base2, h);
                HBAR(mh);   // this half's reads of acts rows complete
                #pragma unroll
                for (int mt = 0; mt < 4; ++mt) {
                    const int row = mh * 64 + mt * 16 + gid;
                    #pragma unroll
                    for (int ns = 0; ns < 4; ++ns) {
                        const uint32_t* c = &h[(mt * 4 + ns) * 2];
                        const int pair = nq * 16 + ns * 4 + tig;
                        uint32_t bb = b2p[pair];
                        uint32_t p01 = tanh_f16x2(hadd2(c[0], bb));
                        uint32_t p23 = tanh_f16x2(hadd2(c[1], bb));
                        *(uint32_t*)(smem + SM_ACT + row * PFB + pair * 4) = p01;
                        *(uint32_t*)(smem + SM_ACT + (row + 8) * PFB + pair * 4) = p23;
                    }
                }
            }
            HBAR(mh);   // this half's acts2 rows written

            // ---- layer 3: GEMM (f16 acc) + packed bias+tanh + W4 dot ----
            {
                uint32_t h[32];
                gemm128_h(a_base, b_base3, h);
                #pragma unroll
                for (int mt = 0; mt < 4; ++mt) {
                    float p0 = 0.0f, p1 = 0.0f;
                    #pragma unroll
                    for (int ns = 0; ns < 4; ++ns) {
                        const uint32_t* c = &h[(mt * 4 + ns) * 2];
                        const int pair = nq * 16 + ns * 4 + tig;
                        uint32_t bb = b3p[pair];
                        float w0 = w4s[2 * pair], w1 = w4s[2 * pair + 1];
                        float2 f01 = unpack_h2(tanh_f16x2(hadd2(c[0], bb)));
                        float2 f23 = unpack_h2(tanh_f16x2(hadd2(c[1], bb)));
                        p0 = fmaf(f01.x, w0, p0);
                        p0 = fmaf(f01.y, w1, p0);
                        p1 = fmaf(f23.x, w0, p1);
                        p1 = fmaf(f23.y, w1, p1);
                    }
                    p0 += __shfl_xor_sync(0xFFFFFFFFu, p0, 1);
                    p0 += __shfl_xor_sync(0xFFFFFFFFu, p0, 2);
                    p1 += __shfl_xor_sync(0xFFFFFFFFu, p1, 1);
                    p1 += __shfl_xor_sync(0xFFFFFFFFu, p1, 2);
                    if (tig == 0) {
                        const int row = mh * 64 + mt * 16 + gid;
                        part[nq * 128 + row]     = p0;
                        part[nq * 128 + row + 8] = p1;
                    }
                }
            }
            __syncthreads();   // full: part read crosses halves; next layer-1 too

            // ---- recon + squared error ----
            if (tid < 128) {
                const int p = tid;
                float recon = b4v + part[p] + part[128 + p]
                            + part[256 + p] + part[384 + p];
                float e = img - recon;
                lacc = fmaf(e, e, lacc);
            }
        }
    }

    // ---- block reduction (reuses part area; loop is done) ----
    __syncthreads();
    float* red = (float*)(smem + SM_RED);
    red[tid] = lacc;
    __syncthreads();
    #pragma unroll
    for (int s = 128; s > 0; s >>= 1) {
        if (tid < s) red[tid] += red[tid + s];
        __syncthreads();
    }

    // ---- publish partial; last CTA reduces (counter self-wraps per launch) ----
    if (tid == 0) {
        g_partial[blk] = red[0];
        __threadfence();
        unsigned int old = atomicInc(&g_done, GRID - 1);
        s_last = (old == GRID - 1) ? 1u : 0u;
    }
    __syncthreads();
    if (s_last) {
        __threadfence();   // acquire: g_partial writes visible to whole block
        float a = 0.0f;
        for (int i = tid; i < GRID; i += 256) a += g_partial[i];
        red[tid] = a;
        __syncthreads();
        #pragma unroll
        for (int s = 128; s > 0; s >>= 1) {
            if (tid < s) red[tid] += red[tid + s];
            __syncthreads();
        }
        if (tid == 0)
            out[0] = red[0] * (1.0f / (float)(BB * 256 * 256));
    }
}

extern "C" void kernel_launch(void* const* d_in, const int* in_sizes, int n_in,
                              void* d_out, int out_size)
{
    const float* images = (const float*)d_in[0];
    const float* W1     = (const float*)d_in[1];
    const float* b1     = (const float*)d_in[2];
    const float* W2     = (const float*)d_in[3];
    const float* b2     = (const float*)d_in[4];
    const float* W3     = (const float*)d_in[5];
    const float* b3     = (const float*)d_in[6];
    const float* W4     = (const float*)d_in[7];
    const float* b4     = (const float*)d_in[8];
    const int*   nptr   = (n_in > 10) ? (const int*)d_in[10] : nullptr;

    cudaFuncSetAttribute(mlp_mma_kernel,
                         cudaFuncAttributeMaxDynamicSharedMemorySize, SM_TOTAL);

    mlp_mma_kernel<<<GRID, 256, SM_TOTAL>>>(images, W1, b1, W2, b2,
                                            W3, b3, W4, b4, nptr,
                                            (float*)d_out);
}